// round 16
// baseline (speedup 1.0000x reference)
#include <cuda_runtime.h>
#include <math_constants.h>

#define NPTS  4096
#define NB    4
#define KNN   16
#define DFEAT 64
#define DOUT  128
#define CH_STRIDE 65536   // NPTS*KNN
#define CHUNK 2048        // candidates staged per smem chunk (32KB float4)
#define HALFQ 1024        // candidates per thread per chunk
#define QPB   64          // queries per block

// Scratch (device globals; no allocation allowed)
__device__ float4 g_coords4[NB * NPTS];          // (x,y,z,|c|^2)
__device__ int    g_idx [NB * NPTS * KNN];
__device__ float  g_dist[NB * NPTS * KNN];

// ---------------------------------------------------------------------------
// Kernel A: pack coords into float4 with precomputed squared norm
// ---------------------------------------------------------------------------
__global__ void build_coords4_k(const float* __restrict__ coords) {
    int p = blockIdx.x * blockDim.x + threadIdx.x;
    if (p < NB * NPTS) {
        float x = coords[3 * p + 0];
        float y = coords[3 * p + 1];
        float z = coords[3 * p + 2];
        float sq = fmaf(z, z, fmaf(y, y, x * x));
        g_coords4[p] = make_float4(x, y, z, sq);
    }
}

// ---------------------------------------------------------------------------
// Kernel B: exact KNN (K=16), TWO threads per query. Each thread scans a
// disjoint 2048-candidate half (1024 per chunk), keeps a private sorted
// top-16 on key = |c|^2 - 2*dot(q,c) (== d2 - |q|^2, order-equivalent).
// Early-exit tail insertion; bd[s-1] <= key stops the shift so equal keys
// keep the earlier (smaller-j) element ahead. The thread pair then merges
// 2x16 sorted lists with lexicographic (key, j) compare — exactly
// lax.top_k's ascending (d2, index) order, including cross-half ties.
//
// FUSED: the 64 KNN-independent feature channels of the output are written
// here (each half-thread owns 32 channels, one per 64-candidate group),
// draining their 67MB of stores under the scan's compute time.
//
// __launch_bounds__(128,2): <=128 regs, 2 blocks/SM -> ~1.7 warps/SMSP.
// ---------------------------------------------------------------------------
__global__ void __launch_bounds__(128, 2) knn_k(const float* __restrict__ features,
                                                float* __restrict__ out) {
    __shared__ float4 sc[CHUNK];   // 32KB; reused as merge buffer afterwards

    int b     = blockIdx.x >> 6;                 // 64 blocks per batch
    int qbase = (blockIdx.x & 63) * QPB;
    int ql    = threadIdx.x & (QPB - 1);         // query within block
    int half  = threadIdx.x >> 6;                // 0 or 1 (warp-constant)
    int qi    = qbase + ql;

    const float4* cb = g_coords4 + b * NPTS;
    float4 q = cb[qi];

    const float* fp = features + b * DFEAT * NPTS + qi;
    float* opb = out + (b * 192 + DOUT) * CH_STRIDE + qi * KNN;

    float bd[KNN];   // keys (d2 - q.w), ascending
    int   bj[KNN];
#pragma unroll
    for (int s = 0; s < KNN; s++) { bd[s] = CUDART_INF_F; bj[s] = 0; }

    for (int cidx = 0; cidx < 2; cidx++) {
        int j0 = cidx * CHUNK;
        __syncthreads();
        for (int p = threadIdx.x; p < CHUNK; p += 128) sc[p] = cb[j0 + p];
        __syncthreads();

        int sbase = half * HALFQ;            // this thread's sub-range in sc
        int jg0   = j0 + sbase;              // global j of sub-range start
        int ch0   = half * 32 + cidx * 16;   // 16 feature channels this chunk
        float f = fp[ch0 * NPTS];            // prefetch first channel value

        for (int g = 0; g < 16; g++) {       // 16 groups of 64 candidates
            float fcur = f;
            if (g + 1 < 16) f = fp[(ch0 + g + 1) * NPTS];

            int jb = g * 64;
#pragma unroll 8
            for (int jl = jb; jl < jb + 64; jl++) {
                float4 c = sc[sbase + jl];
                float dot = fmaf(q.z, c.z, fmaf(q.y, c.y, q.x * c.x));
                float key = fmaf(-2.0f, dot, c.w);
                if (key < bd[KNN - 1]) {
                    int idx = jg0 + jl;
                    // early-exit tail insertion
#pragma unroll
                    for (int s = KNN - 1; s >= 0; --s) {
                        if (s == 0 || bd[s - 1] <= key) {
                            bd[s] = key; bj[s] = idx;
                            break;
                        }
                        bd[s] = bd[s - 1]; bj[s] = bj[s - 1];
                    }
                }
            }

            // interleaved feature store: channel ch0+g, 16 k (4xSTG.128)
            float4 v = make_float4(fcur, fcur, fcur, fcur);
            float4* o = (float4*)(opb + (ch0 + g) * CH_STRIDE);
            o[0] = v; o[1] = v; o[2] = v; o[3] = v;
        }
    }

    // ---- pair merge: reuse sc as [64][2][16] key + [64][2][16] idx ----
    __syncthreads();
    float* mkey = (float*)sc;                    // 2048 floats (8KB)
    int*   midx = (int*)((float*)sc + 2048);     // 2048 ints   (8KB)
    int lst = (ql * 2 + half) * KNN;
#pragma unroll
    for (int s = 0; s < KNN; s++) { mkey[lst + s] = bd[s]; midx[lst + s] = bj[s]; }
    __syncthreads();

    if (half == 0) {
        const float* k0 = mkey + (ql * 2 + 0) * KNN;
        const float* k1 = mkey + (ql * 2 + 1) * KNN;
        const int*   x0 = midx + (ql * 2 + 0) * KNN;
        const int*   x1 = midx + (ql * 2 + 1) * KNN;

        float rk[KNN]; int rj[KNN];
        int i0 = 0, i1 = 0;
#pragma unroll
        for (int s = 0; s < KNN; s++) {          // i0,i1 <= 15 at read time
            float ka = k0[i0], kb = k1[i1];
            int   ja = x0[i0], jb = x1[i1];
            bool takeA = (ka < kb) || (ka == kb && ja < jb);
            rk[s] = takeA ? ka : kb;
            rj[s] = takeA ? ja : jb;
            if (takeA) i0++; else i1++;
        }

        int base = (b * NPTS + qi) * KNN;
#pragma unroll
        for (int v4 = 0; v4 < KNN / 4; v4++) {
            int4 iv = make_int4(rj[v4 * 4 + 0], rj[v4 * 4 + 1],
                                rj[v4 * 4 + 2], rj[v4 * 4 + 3]);
            float4 dv = make_float4(sqrtf(fmaxf(q.w + rk[v4 * 4 + 0], 1e-12f)),
                                    sqrtf(fmaxf(q.w + rk[v4 * 4 + 1], 1e-12f)),
                                    sqrtf(fmaxf(q.w + rk[v4 * 4 + 2], 1e-12f)),
                                    sqrtf(fmaxf(q.w + rk[v4 * 4 + 3], 1e-12f)));
            *(int4*)  (g_idx  + base + v4 * 4) = iv;
            *(float4*)(g_dist + base + v4 * 4) = dv;
        }
    }
}

// ---------------------------------------------------------------------------
// Kernel C: encoding + 1x1-conv MLP (128 channels; feature channels already
// written by knn_k). Factored weights:
//   r_c = (Wa+Wc)·pi + (Wb−Wc)·pj + w9·d + b   (u = Wa+Wc, v = Wb−Wc)
// 19 FMA/channel vs 40 naive. Stores STG.128, warp-contiguous 512B/row.
// ---------------------------------------------------------------------------
__global__ void __launch_bounds__(128) out_k(const float* __restrict__ W,
                                             const float* __restrict__ bias,
                                             float* __restrict__ out) {
    __shared__ float sW[DOUT * 8];   // per ch: u0,u1,u2,v0, v1,v2,w9,b
    int t = threadIdx.x;
    for (int c = t; c < DOUT; c += 128) {
        const float* w = W + c * 10;
        sW[c * 8 + 0] = w[0] + w[6];
        sW[c * 8 + 1] = w[1] + w[7];
        sW[c * 8 + 2] = w[2] + w[8];
        sW[c * 8 + 3] = w[3] - w[6];
        sW[c * 8 + 4] = w[4] - w[7];
        sW[c * 8 + 5] = w[5] - w[8];
        sW[c * 8 + 6] = w[9];
        sW[c * 8 + 7] = bias[c];
    }
    __syncthreads();

    int tid = blockIdx.x * 128 + t;
    int k4  = tid & 3;
    int n   = (tid >> 2) & (NPTS - 1);
    int b   = tid >> 14;

    float4 pi = g_coords4[b * NPTS + n];

    int base = (b * NPTS + n) * KNN + k4 * 4;
    int4   jj = *(const int4*)  (g_idx  + base);
    float4 dd = *(const float4*)(g_dist + base);

    float4 pj0 = g_coords4[b * NPTS + jj.x];
    float4 pj1 = g_coords4[b * NPTS + jj.y];
    float4 pj2 = g_coords4[b * NPTS + jj.z];
    float4 pj3 = g_coords4[b * NPTS + jj.w];

    int ob = b * 192 * CH_STRIDE + n * KNN + k4 * 4;

#pragma unroll 4
    for (int c = 0; c < DOUT; c++) {
        float4 wa = *(const float4*)(sW + c * 8);      // u0,u1,u2,v0
        float4 wb = *(const float4*)(sW + c * 8 + 4);  // v1,v2,w9,b
        float bse = fmaf(wa.z, pi.z, fmaf(wa.y, pi.y, fmaf(wa.x, pi.x, wb.w)));
        float4 r;
        r.x = fmaf(wb.z, dd.x, fmaf(wb.y, pj0.z, fmaf(wb.x, pj0.y, fmaf(wa.w, pj0.x, bse))));
        r.y = fmaf(wb.z, dd.y, fmaf(wb.y, pj1.z, fmaf(wb.x, pj1.y, fmaf(wa.w, pj1.x, bse))));
        r.z = fmaf(wb.z, dd.z, fmaf(wb.y, pj2.z, fmaf(wb.x, pj2.y, fmaf(wa.w, pj2.x, bse))));
        r.w = fmaf(wb.z, dd.w, fmaf(wb.y, pj3.z, fmaf(wb.x, pj3.y, fmaf(wa.w, pj3.x, bse))));
        *(float4*)(out + ob + c * CH_STRIDE) = r;
    }
}

// ---------------------------------------------------------------------------
extern "C" void kernel_launch(void* const* d_in, const int* in_sizes, int n_in,
                              void* d_out, int out_size) {
    const float* coords   = (const float*)d_in[0];
    const float* features = (const float*)d_in[1];
    const float* W        = (const float*)d_in[2];
    const float* bias     = (const float*)d_in[3];
    float* out = (float*)d_out;

    build_coords4_k<<<(NB * NPTS + 255) / 256, 256>>>(coords);
    knn_k<<<NB * QPB, 128>>>(features, out);
    out_k<<<(NB * NPTS * 4) / 128, 128>>>(W, bias, out);
}